// round 3
// baseline (speedup 1.0000x reference)
#include <cuda_runtime.h>
#include <cuda_fp16.h>

#define HIDDEN    64
#define N_USERS   100000
#define N_MOVIES  50000
#define MOVIE_FEAT 128
#define N_EDGES   2000000
#define N_LABEL   500000

// padded so the single-block scans can read int4 past n without guards
#define NM_PAD (N_MOVIES + 8192)
#define NU_PAD (N_USERS  + 8192)

// ---------------- device scratch (allocation-free rule: __device__ globals) ----------------
__device__ __align__(16) int g_deg_m[NM_PAD];
__device__ __align__(16) int g_deg_u[NU_PAD];
__device__ __align__(16) int g_off_m[NM_PAD];
__device__ __align__(16) int g_off_u[NU_PAD];
__device__ __align__(16) int g_cur_m[NM_PAD];
__device__ __align__(16) int g_cur_u[NU_PAD];
__device__ int g_csr_m[N_EDGES];   // neighbors (user idx) of each movie, CSR by movie
__device__ int g_csr_u[N_EDGES];   // neighbors (movie idx) of each user, CSR by user
__device__ __align__(16) float g_xu[N_USERS  * HIDDEN];
__device__ __align__(16) float g_xm[N_MOVIES * HIDDEN];
__device__ __align__(16) float g_hu[N_USERS  * HIDDEN];
__device__ __align__(16) float g_hm[N_MOVIES * HIDDEN];
__device__ __align__(16) float g_mu[N_USERS  * HIDDEN];
__device__ __align__(16) float g_mm[N_MOVIES * HIDDEN];
// fp16 copies used ONLY as aggregation gather sources (halve L2 traffic)
__device__ __align__(16) __half g_f16u[N_USERS  * HIDDEN];
__device__ __align__(16) __half g_f16m[N_MOVIES * HIDDEN];

// ---------------- packed f32x2 helpers (FFMA2 on sm_103a) ----------------
__device__ __forceinline__ unsigned long long pack2(float lo, float hi)
{
    unsigned long long r;
    asm("mov.b64 %0, {%1, %2};" : "=l"(r) : "f"(lo), "f"(hi));
    return r;
}
__device__ __forceinline__ void unpack2(unsigned long long v, float& lo, float& hi)
{
    asm("mov.b64 {%0, %1}, %2;" : "=f"(lo), "=f"(hi) : "l"(v));
}
__device__ __forceinline__ unsigned long long ffma2(unsigned long long a,
                                                    unsigned long long b,
                                                    unsigned long long c)
{
    unsigned long long d;
    asm("fma.rn.f32x2 %0, %1, %2, %3;" : "=l"(d) : "l"(a), "l"(b), "l"(c));
    return d;
}

// ---------------- CSR build ----------------
__global__ void zero_deg_kernel()
{
    int i = blockIdx.x * blockDim.x + threadIdx.x;
    int4 z = make_int4(0, 0, 0, 0);
    if (i < NM_PAD / 4) ((int4*)g_deg_m)[i] = z;
    if (i < NU_PAD / 4) ((int4*)g_deg_u)[i] = z;
}

__global__ void hist_kernel(const int* __restrict__ src, const int* __restrict__ dst)
{
    int i = blockIdx.x * blockDim.x + threadIdx.x;
    if (i >= N_EDGES) return;
    atomicAdd(&g_deg_u[src[i]], 1);
    atomicAdd(&g_deg_m[dst[i]], 1);
}

// block 0 scans movie degrees, block 1 scans user degrees; also initializes cursors
__global__ __launch_bounds__(1024) void scan_kernel()
{
    int n; int* deg; int* off; int* cur;
    if (blockIdx.x == 0) { n = N_MOVIES; deg = g_deg_m; off = g_off_m; cur = g_cur_m; }
    else                 { n = N_USERS;  deg = g_deg_u; off = g_off_u; cur = g_cur_u; }
    int chunk = ((((n + 1023) >> 10) + 3) & ~3);   // multiple of 4 for int4
    int t = threadIdx.x;
    int start = t * chunk;

    int s = 0;
    for (int i = 0; i < chunk; i += 4) {
        int4 v = *(const int4*)(deg + start + i);
        s += v.x + v.y + v.z + v.w;
    }
    __shared__ int sh[1024];
    sh[t] = s; __syncthreads();
    for (int d = 1; d < 1024; d <<= 1) {
        int v = (t >= d) ? sh[t - d] : 0;
        __syncthreads();
        sh[t] += v;
        __syncthreads();
    }
    int run = t ? sh[t - 1] : 0;
    for (int i = 0; i < chunk; i += 4) {
        int4 v = *(const int4*)(deg + start + i);
        int4 o;
        o.x = run; run += v.x;
        o.y = run; run += v.y;
        o.z = run; run += v.z;
        o.w = run; run += v.w;
        *(int4*)(off + start + i) = o;
        *(int4*)(cur + start + i) = o;
    }
}

__global__ void scatter_kernel(const int* __restrict__ src, const int* __restrict__ dst)
{
    int i = blockIdx.x * blockDim.x + threadIdx.x;
    if (i >= N_EDGES) return;
    int u = src[i], m = dst[i];
    g_csr_m[atomicAdd(&g_cur_m[m], 1)] = u;
    g_csr_u[atomicAdd(&g_cur_u[u], 1)] = m;
}

// ---------------- feature init ----------------
__global__ void gather_user_kernel(const float* __restrict__ emb,
                                   const int* __restrict__ nid,
                                   float* __restrict__ xu, __half* __restrict__ xu16)
{
    int i = blockIdx.x * blockDim.x + threadIdx.x;   // over N_USERS*16 float4s
    if (i >= N_USERS * 16) return;
    int r = i >> 4, c = i & 15;
    float4 v = __ldg((const float4*)emb + nid[r] * 16 + c);
    ((float4*)xu)[i] = v;
    __half2 h0 = __floats2half2_rn(v.x, v.y);
    __half2 h1 = __floats2half2_rn(v.z, v.w);
    uint2 o;
    o.x = *(unsigned int*)&h0;
    o.y = *(unsigned int*)&h1;
    ((uint2*)xu16)[i] = o;
}

// x_movie = movie_x @ lin_W^T + lin_b + movie_emb[movie_nid]
// 256 threads = 4 groups of 64; each group does 8 rows per iteration.
__global__ __launch_bounds__(256) void movie_init_kernel(
    const float* __restrict__ movie_x, const float* __restrict__ lin_W,
    const float* __restrict__ lin_b,  const float* __restrict__ movie_emb,
    const int* __restrict__ movie_nid, float* __restrict__ xm,
    __half* __restrict__ xm16, int n)
{
    __shared__ float4 srow[4][8][32];
    int j = threadIdx.x & 63, g = threadIdx.x >> 6;
    unsigned long long w01[32], w23[32];
#pragma unroll
    for (int k = 0; k < 32; k++) {
        float4 t = __ldg((const float4*)lin_W + j * 32 + k);
        w01[k] = pack2(t.x, t.y);
        w23[k] = pack2(t.z, t.w);
    }
    float bj = __ldg(lin_b + j);
    for (int r0 = blockIdx.x * 32; r0 < n; r0 += gridDim.x * 32) {
        int rbase = r0 + g * 8;
#pragma unroll
        for (int p = 0; p < 4; p++) {
            int item = p * 64 + j;
            int row = item >> 5, col = item & 31;
            int r = rbase + row;
            if (r < n)
                srow[g][row][col] = __ldg((const float4*)movie_x + (size_t)r * 32 + col);
        }
        __syncthreads();
#pragma unroll
        for (int rr = 0; rr < 8; rr++) {
            int r = rbase + rr;
            if (r < n) {
                unsigned long long p0 = 0, p1 = 0;   // packed (0.f, 0.f)
#pragma unroll
                for (int k = 0; k < 32; k++) {
                    ulonglong2 v = *(const ulonglong2*)&srow[g][rr][k];
                    p0 = ffma2(v.x, w01[k], p0);
                    p1 = ffma2(v.y, w23[k], p1);
                }
                float a0, a1, a2, a3;
                unpack2(p0, a0, a1); unpack2(p1, a2, a3);
                int nid = __ldg(movie_nid + r);
                float res = (a0 + a1) + (a2 + a3) + bj +
                            __ldg(movie_emb + (size_t)nid * 64 + j);
                xm[(size_t)r * 64 + j] = res;
                xm16[(size_t)r * 64 + j] = __float2half(res);
            }
        }
        __syncthreads();
    }
}

// ---------------- segment mean, both directions fused (half-warp per node, fp16 src) ------
__global__ void aggregate2_kernel(const __half* __restrict__ src_for_m,  // user feats fp16
                                  const __half* __restrict__ src_for_u,  // movie feats fp16
                                  float* __restrict__ out_m, float* __restrict__ out_u)
{
    int h = (blockIdx.x * blockDim.x + threadIdx.x) >> 4;
    int lane = threadIdx.x & 15;
    const uint2* xsrc; const int* csr; const int* off; float* mean; int node;
    if (h < N_MOVIES) {
        node = h; xsrc = (const uint2*)src_for_m; csr = g_csr_m; off = g_off_m; mean = out_m;
    } else {
        node = h - N_MOVIES;
        if (node >= N_USERS) return;
        xsrc = (const uint2*)src_for_u; csr = g_csr_u; off = g_off_u; mean = out_u;
    }
    int s0 = __ldg(off + node), s1 = __ldg(off + node + 1);
    int deg = s1 - s0;
    const int* nb = csr + s0;
    float ax = 0, ay = 0, az = 0, aw = 0;
    float bx = 0, by = 0, bz = 0, bw = 0;
    int i = 0;
    for (; i + 4 <= deg; i += 4) {
        int n0 = __ldg(nb + i),     n1 = __ldg(nb + i + 1);
        int n2 = __ldg(nb + i + 2), n3 = __ldg(nb + i + 3);
        uint2 v0 = __ldg(xsrc + n0 * 16 + lane);
        uint2 v1 = __ldg(xsrc + n1 * 16 + lane);
        uint2 v2 = __ldg(xsrc + n2 * 16 + lane);
        uint2 v3 = __ldg(xsrc + n3 * 16 + lane);
        float2 f;
        f = __half22float2(*(__half2*)&v0.x); ax += f.x; ay += f.y;
        f = __half22float2(*(__half2*)&v0.y); az += f.x; aw += f.y;
        f = __half22float2(*(__half2*)&v1.x); bx += f.x; by += f.y;
        f = __half22float2(*(__half2*)&v1.y); bz += f.x; bw += f.y;
        f = __half22float2(*(__half2*)&v2.x); ax += f.x; ay += f.y;
        f = __half22float2(*(__half2*)&v2.y); az += f.x; aw += f.y;
        f = __half22float2(*(__half2*)&v3.x); bx += f.x; by += f.y;
        f = __half22float2(*(__half2*)&v3.y); bz += f.x; bw += f.y;
    }
    for (; i < deg; i++) {
        int n0 = __ldg(nb + i);
        uint2 v = __ldg(xsrc + n0 * 16 + lane);
        float2 f;
        f = __half22float2(*(__half2*)&v.x); ax += f.x; ay += f.y;
        f = __half22float2(*(__half2*)&v.y); az += f.x; aw += f.y;
    }
    float inv = deg > 0 ? 1.0f / (float)deg : 0.0f;   // deg==0 -> mean 0, matches reference
    float4 o;
    o.x = (ax + bx) * inv; o.y = (ay + by) * inv;
    o.z = (az + bz) * inv; o.w = (aw + bw) * inv;
    ((float4*)mean)[node * 16 + lane] = o;
}

// ---------------- SAGE transform, both edge types fused into one launch ----------------
// out = mean@Wl^T + bl + x@Wr^T (optional relu). 4 groups x 8 rows per block-iteration.
template<bool RELU>
__global__ __launch_bounds__(256) void transform2_kernel(
    const float* __restrict__ mean_m, const float* __restrict__ xd_m,
    const float* __restrict__ Wl_m, const float* __restrict__ bl_m,
    const float* __restrict__ Wr_m, float* __restrict__ out_m, __half* __restrict__ o16_m,
    const float* __restrict__ mean_u, const float* __restrict__ xd_u,
    const float* __restrict__ Wl_u, const float* __restrict__ bl_u,
    const float* __restrict__ Wr_u, float* __restrict__ out_u, __half* __restrict__ o16_u,
    int nb_m)
{
    __shared__ float4 sm[4][8][2][16];
    const float *mean, *xd, *Wl, *bl, *Wr; float* out; __half* o16; int n, bid, nb;
    if ((int)blockIdx.x < nb_m) {
        mean = mean_m; xd = xd_m; Wl = Wl_m; bl = bl_m; Wr = Wr_m; out = out_m; o16 = o16_m;
        n = N_MOVIES; bid = blockIdx.x; nb = nb_m;
    } else {
        mean = mean_u; xd = xd_u; Wl = Wl_u; bl = bl_u; Wr = Wr_u; out = out_u; o16 = o16_u;
        n = N_USERS; bid = blockIdx.x - nb_m; nb = gridDim.x - nb_m;
    }
    int j = threadIdx.x & 63, g = threadIdx.x >> 6;
    unsigned long long wl01[16], wl23[16], wr01[16], wr23[16];
#pragma unroll
    for (int k = 0; k < 16; k++) {
        float4 a = __ldg((const float4*)Wl + j * 16 + k);
        wl01[k] = pack2(a.x, a.y); wl23[k] = pack2(a.z, a.w);
        float4 b = __ldg((const float4*)Wr + j * 16 + k);
        wr01[k] = pack2(b.x, b.y); wr23[k] = pack2(b.z, b.w);
    }
    float bj = __ldg(bl + j);
    for (int r0 = bid * 32; r0 < n; r0 += nb * 32) {
        int rbase = r0 + g * 8;
#pragma unroll
        for (int p = 0; p < 4; p++) {
            int item = p * 64 + j;
            int row = item >> 5, sel = (item >> 4) & 1, col = item & 15;
            int r = rbase + row;
            if (r < n) {
                const float* src = sel ? xd : mean;
                sm[g][row][sel][col] = __ldg((const float4*)src + (size_t)r * 16 + col);
            }
        }
        __syncthreads();
#pragma unroll
        for (int rr = 0; rr < 8; rr++) {
            int r = rbase + rr;
            if (r < n) {
                unsigned long long p0 = 0, p1 = 0, p2 = 0, p3 = 0;
#pragma unroll
                for (int k = 0; k < 16; k++) {
                    ulonglong2 m = *(const ulonglong2*)&sm[g][rr][0][k];
                    ulonglong2 x = *(const ulonglong2*)&sm[g][rr][1][k];
                    p0 = ffma2(m.x, wl01[k], p0);
                    p1 = ffma2(m.y, wl23[k], p1);
                    p2 = ffma2(x.x, wr01[k], p2);
                    p3 = ffma2(x.y, wr23[k], p3);
                }
                float a0, a1, a2, a3, a4, a5, a6, a7;
                unpack2(p0, a0, a1); unpack2(p1, a2, a3);
                unpack2(p2, a4, a5); unpack2(p3, a6, a7);
                float res = bj + (((a0 + a1) + (a2 + a3)) + ((a4 + a5) + (a6 + a7)));
                if (RELU) {
                    res = fmaxf(res, 0.0f);
                    o16[(size_t)r * 64 + j] = __float2half(res);
                }
                out[(size_t)r * 64 + j] = res;
            }
        }
        __syncthreads();
    }
}

// ---------------- dot-product decoder (half-warp per edge, float4) ----------------
__global__ void decode_kernel(const float* __restrict__ ou, const float* __restrict__ om,
                              const int* __restrict__ ls, const int* __restrict__ ld,
                              float* __restrict__ out, int n)
{
    int e = (blockIdx.x * blockDim.x + threadIdx.x) >> 4;
    int lane = threadIdx.x & 15;
    if (e >= n) return;
    int u = __ldg(ls + e), m = __ldg(ld + e);
    float4 a = __ldg((const float4*)ou + u * 16 + lane);
    float4 b = __ldg((const float4*)om + m * 16 + lane);
    float p = a.x * b.x + a.y * b.y + a.z * b.z + a.w * b.w;
    p += __shfl_xor_sync(0xffffffffu, p, 1);
    p += __shfl_xor_sync(0xffffffffu, p, 2);
    p += __shfl_xor_sync(0xffffffffu, p, 4);
    p += __shfl_xor_sync(0xffffffffu, p, 8);
    if (lane == 0) out[e] = p;
}

// ---------------- launch ----------------
extern "C" void kernel_launch(void* const* d_in, const int* in_sizes, int n_in,
                              void* d_out, int out_size)
{
    const float* movie_x   = (const float*)d_in[0];
    const int*   user_nid  = (const int*)d_in[1];
    const int*   movie_nid = (const int*)d_in[2];
    const int*   e_src     = (const int*)d_in[3];
    const int*   e_dst     = (const int*)d_in[4];
    const int*   l_src     = (const int*)d_in[5];
    const int*   l_dst     = (const int*)d_in[6];
    const float* user_emb  = (const float*)d_in[7];
    const float* movie_emb = (const float*)d_in[8];
    const float* lin_W     = (const float*)d_in[9];
    const float* lin_b     = (const float*)d_in[10];
    const float* W_l_um1 = (const float*)d_in[11];
    const float* b_l_um1 = (const float*)d_in[12];
    const float* W_r_um1 = (const float*)d_in[13];
    const float* W_l_mu1 = (const float*)d_in[14];
    const float* b_l_mu1 = (const float*)d_in[15];
    const float* W_r_mu1 = (const float*)d_in[16];
    const float* W_l_um2 = (const float*)d_in[17];
    const float* b_l_um2 = (const float*)d_in[18];
    const float* W_r_um2 = (const float*)d_in[19];
    const float* W_l_mu2 = (const float*)d_in[20];
    const float* b_l_mu2 = (const float*)d_in[21];
    const float* W_r_mu2 = (const float*)d_in[22];
    float* out = (float*)d_out;

    float *xu, *xm, *hu, *hm, *mu, *mm;
    __half *f16u, *f16m;
    cudaGetSymbolAddress((void**)&xu, g_xu);
    cudaGetSymbolAddress((void**)&xm, g_xm);
    cudaGetSymbolAddress((void**)&hu, g_hu);
    cudaGetSymbolAddress((void**)&hm, g_hm);
    cudaGetSymbolAddress((void**)&mu, g_mu);
    cudaGetSymbolAddress((void**)&mm, g_mm);
    cudaGetSymbolAddress((void**)&f16u, g_f16u);
    cudaGetSymbolAddress((void**)&f16m, g_f16m);

    // CSR build (reused by both layers, both directions)
    zero_deg_kernel<<<(NU_PAD / 4 + 255) / 256, 256>>>();
    hist_kernel<<<(N_EDGES + 255) / 256, 256>>>(e_src, e_dst);
    scan_kernel<<<2, 1024>>>();   // also writes cursors
    scatter_kernel<<<(N_EDGES + 255) / 256, 256>>>(e_src, e_dst);

    // feature init (fp32 + fp16 copies)
    gather_user_kernel<<<(N_USERS * 16 + 255) / 256, 256>>>(user_emb, user_nid, xu, f16u);
    movie_init_kernel<<<592, 256>>>(movie_x, lin_W, lin_b, movie_emb, movie_nid,
                                    xm, f16m, N_MOVIES);

    const int AGG_BLOCKS = ((N_MOVIES + N_USERS) * 16 + 255) / 256;

    // layer 1 (+relu); transform writes fp32 h and fp16 copies (overwriting x16 after agg)
    aggregate2_kernel<<<AGG_BLOCKS, 256>>>(f16u, f16m, mm, mu);
    transform2_kernel<true><<<592, 256>>>(mm, xm, W_l_um1, b_l_um1, W_r_um1, hm, f16m,
                                          mu, xu, W_l_mu1, b_l_mu1, W_r_mu1, hu, f16u, 197);

    // layer 2 (no activation); outputs overwrite x buffers
    aggregate2_kernel<<<AGG_BLOCKS, 256>>>(f16u, f16m, mm, mu);
    transform2_kernel<false><<<592, 256>>>(mm, hm, W_l_um2, b_l_um2, W_r_um2, xm, nullptr,
                                           mu, hu, W_l_mu2, b_l_mu2, W_r_mu2, xu, nullptr, 197);

    // decoder
    decode_kernel<<<(N_LABEL * 16 + 255) / 256, 256>>>(xu, xm, l_src, l_dst, out, N_LABEL);
}

// round 4
// speedup vs baseline: 1.0344x; 1.0344x over previous
#include <cuda_runtime.h>
#include <cuda_fp16.h>

#define HIDDEN    64
#define N_USERS   100000
#define N_MOVIES  50000
#define MOVIE_FEAT 128
#define N_EDGES   2000000
#define N_LABEL   500000

// padded so the single-block scans can read int4 past n without guards
#define NM_PAD (N_MOVIES + 8192)
#define NU_PAD (N_USERS  + 8192)

// ---------------- device scratch (allocation-free rule: __device__ globals) ----------------
__device__ __align__(16) int g_deg_m[NM_PAD];
__device__ __align__(16) int g_deg_u[NU_PAD];
__device__ __align__(16) int g_off_m[NM_PAD];
__device__ __align__(16) int g_off_u[NU_PAD];
__device__ __align__(16) int g_cur_m[NM_PAD];
__device__ __align__(16) int g_cur_u[NU_PAD];
__device__ int g_csr_m[N_EDGES];   // neighbors (user idx) of each movie, CSR by movie
__device__ int g_csr_u[N_EDGES];   // neighbors (movie idx) of each user, CSR by user
// fp16 node feature buffers (the only feature storage; fp32 only for means)
__device__ __align__(16) __half g_x16u[N_USERS  * HIDDEN];
__device__ __align__(16) __half g_x16m[N_MOVIES * HIDDEN];
__device__ __align__(16) __half g_h16u[N_USERS  * HIDDEN];
__device__ __align__(16) __half g_h16m[N_MOVIES * HIDDEN];
__device__ __align__(16) float g_mu[N_USERS  * HIDDEN];
__device__ __align__(16) float g_mm[N_MOVIES * HIDDEN];

// ---------------- packed f32x2 helpers (FFMA2/FADD2 on sm_103a) ----------------
__device__ __forceinline__ unsigned long long pack2(float lo, float hi)
{
    unsigned long long r;
    asm("mov.b64 %0, {%1, %2};" : "=l"(r) : "f"(lo), "f"(hi));
    return r;
}
__device__ __forceinline__ void unpack2(unsigned long long v, float& lo, float& hi)
{
    asm("mov.b64 {%0, %1}, %2;" : "=f"(lo), "=f"(hi) : "l"(v));
}
__device__ __forceinline__ unsigned long long ffma2(unsigned long long a,
                                                    unsigned long long b,
                                                    unsigned long long c)
{
    unsigned long long d;
    asm("fma.rn.f32x2 %0, %1, %2, %3;" : "=l"(d) : "l"(a), "l"(b), "l"(c));
    return d;
}
__device__ __forceinline__ unsigned long long fadd2(unsigned long long a,
                                                    unsigned long long b)
{
    unsigned long long d;
    asm("add.rn.f32x2 %0, %1, %2;" : "=l"(d) : "l"(a), "l"(b));
    return d;
}

// ---------------- CSR build ----------------
__global__ void zero_deg_kernel()
{
    int i = blockIdx.x * blockDim.x + threadIdx.x;
    int4 z = make_int4(0, 0, 0, 0);
    if (i < NM_PAD / 4) ((int4*)g_deg_m)[i] = z;
    if (i < NU_PAD / 4) ((int4*)g_deg_u)[i] = z;
}

__global__ void hist_kernel(const int4* __restrict__ src4, const int4* __restrict__ dst4)
{
    int i = blockIdx.x * blockDim.x + threadIdx.x;
    if (i >= N_EDGES / 4) return;
    int4 s = __ldg(src4 + i), d = __ldg(dst4 + i);
    atomicAdd(&g_deg_u[s.x], 1); atomicAdd(&g_deg_u[s.y], 1);
    atomicAdd(&g_deg_u[s.z], 1); atomicAdd(&g_deg_u[s.w], 1);
    atomicAdd(&g_deg_m[d.x], 1); atomicAdd(&g_deg_m[d.y], 1);
    atomicAdd(&g_deg_m[d.z], 1); atomicAdd(&g_deg_m[d.w], 1);
}

// block 0 scans movie degrees, block 1 scans user degrees; also initializes cursors
__global__ __launch_bounds__(1024) void scan_kernel()
{
    int n; int* deg; int* off; int* cur;
    if (blockIdx.x == 0) { n = N_MOVIES; deg = g_deg_m; off = g_off_m; cur = g_cur_m; }
    else                 { n = N_USERS;  deg = g_deg_u; off = g_off_u; cur = g_cur_u; }
    int chunk = ((((n + 1023) >> 10) + 3) & ~3);   // multiple of 4 for int4
    int t = threadIdx.x;
    int start = t * chunk;

    int s = 0;
    for (int i = 0; i < chunk; i += 4) {
        int4 v = *(const int4*)(deg + start + i);
        s += v.x + v.y + v.z + v.w;
    }
    __shared__ int sh[1024];
    sh[t] = s; __syncthreads();
    for (int d = 1; d < 1024; d <<= 1) {
        int v = (t >= d) ? sh[t - d] : 0;
        __syncthreads();
        sh[t] += v;
        __syncthreads();
    }
    int run = t ? sh[t - 1] : 0;
    for (int i = 0; i < chunk; i += 4) {
        int4 v = *(const int4*)(deg + start + i);
        int4 o;
        o.x = run; run += v.x;
        o.y = run; run += v.y;
        o.z = run; run += v.z;
        o.w = run; run += v.w;
        *(int4*)(off + start + i) = o;
        *(int4*)(cur + start + i) = o;
    }
}

__global__ void scatter_kernel(const int4* __restrict__ src4, const int4* __restrict__ dst4)
{
    int i = blockIdx.x * blockDim.x + threadIdx.x;
    if (i >= N_EDGES / 4) return;
    int4 s = __ldg(src4 + i), d = __ldg(dst4 + i);
    g_csr_m[atomicAdd(&g_cur_m[d.x], 1)] = s.x;
    g_csr_u[atomicAdd(&g_cur_u[s.x], 1)] = d.x;
    g_csr_m[atomicAdd(&g_cur_m[d.y], 1)] = s.y;
    g_csr_u[atomicAdd(&g_cur_u[s.y], 1)] = d.y;
    g_csr_m[atomicAdd(&g_cur_m[d.z], 1)] = s.z;
    g_csr_u[atomicAdd(&g_cur_u[s.z], 1)] = d.z;
    g_csr_m[atomicAdd(&g_cur_m[d.w], 1)] = s.w;
    g_csr_u[atomicAdd(&g_cur_u[s.w], 1)] = d.w;
}

// ---------------- feature init ----------------
__global__ void gather_user_kernel(const float* __restrict__ emb,
                                   const int* __restrict__ nid,
                                   __half* __restrict__ xu16)
{
    int i = blockIdx.x * blockDim.x + threadIdx.x;   // over N_USERS*16 float4s
    if (i >= N_USERS * 16) return;
    int r = i >> 4, c = i & 15;
    float4 v = __ldg((const float4*)emb + nid[r] * 16 + c);
    __half2 h0 = __floats2half2_rn(v.x, v.y);
    __half2 h1 = __floats2half2_rn(v.z, v.w);
    uint2 o;
    o.x = *(unsigned int*)&h0;
    o.y = *(unsigned int*)&h1;
    ((uint2*)xu16)[i] = o;
}

// x_movie = movie_x @ lin_W^T + lin_b + movie_emb[movie_nid]
// 256 threads = 4 groups of 64; each group does 8 rows per iteration.
__global__ __launch_bounds__(256) void movie_init_kernel(
    const float* __restrict__ movie_x, const float* __restrict__ lin_W,
    const float* __restrict__ lin_b,  const float* __restrict__ movie_emb,
    const int* __restrict__ movie_nid, __half* __restrict__ xm16, int n)
{
    __shared__ float4 srow[4][8][32];
    int j = threadIdx.x & 63, g = threadIdx.x >> 6;
    unsigned long long w01[32], w23[32];
#pragma unroll
    for (int k = 0; k < 32; k++) {
        float4 t = __ldg((const float4*)lin_W + j * 32 + k);
        w01[k] = pack2(t.x, t.y);
        w23[k] = pack2(t.z, t.w);
    }
    float bj = __ldg(lin_b + j);
    for (int r0 = blockIdx.x * 32; r0 < n; r0 += gridDim.x * 32) {
        int rbase = r0 + g * 8;
#pragma unroll
        for (int p = 0; p < 4; p++) {
            int item = p * 64 + j;
            int row = item >> 5, col = item & 31;
            int r = rbase + row;
            if (r < n)
                srow[g][row][col] = __ldg((const float4*)movie_x + (size_t)r * 32 + col);
        }
        __syncthreads();
#pragma unroll
        for (int rr = 0; rr < 8; rr++) {
            int r = rbase + rr;
            if (r < n) {
                unsigned long long p0 = 0, p1 = 0;
#pragma unroll
                for (int k = 0; k < 32; k++) {
                    ulonglong2 v = *(const ulonglong2*)&srow[g][rr][k];
                    p0 = ffma2(v.x, w01[k], p0);
                    p1 = ffma2(v.y, w23[k], p1);
                }
                float a0, a1, a2, a3;
                unpack2(p0, a0, a1); unpack2(p1, a2, a3);
                int nid = __ldg(movie_nid + r);
                float res = (a0 + a1) + (a2 + a3) + bj +
                            __ldg(movie_emb + (size_t)nid * 64 + j);
                xm16[(size_t)r * 64 + j] = __float2half(res);
            }
        }
        __syncthreads();
    }
}

// ---------------- segment mean, both directions fused, software-pipelined ----------------
// half-warp per node; 8 independent feature loads in flight; next index chunk prefetched
// while the current chunk's feature loads are outstanding.
__global__ void aggregate2_kernel(const __half* __restrict__ src_for_m,  // user feats fp16
                                  const __half* __restrict__ src_for_u,  // movie feats fp16
                                  float* __restrict__ out_m, float* __restrict__ out_u)
{
    int h = (blockIdx.x * blockDim.x + threadIdx.x) >> 4;
    int lane = threadIdx.x & 15;
    const uint2* xsrc; const int* csr; const int* off; float4* mean; int node;
    if (h < N_MOVIES) {
        node = h; xsrc = (const uint2*)src_for_m; csr = g_csr_m; off = g_off_m;
        mean = (float4*)out_m;
    } else {
        node = h - N_MOVIES;
        if (node >= N_USERS) return;
        xsrc = (const uint2*)src_for_u; csr = g_csr_u; off = g_off_u;
        mean = (float4*)out_u;
    }
    int s0 = __ldg(off + node);
    int deg = __ldg(off + node + 1) - s0;
    const int* nb = csr + s0;

    unsigned long long a01 = 0, a23 = 0, b01 = 0, b23 = 0;
    int nch = deg >> 3;
    int idx[8];
    if (nch > 0) {
#pragma unroll
        for (int k = 0; k < 8; k++) idx[k] = __ldg(nb + k);
        for (int c = 0; c < nch; c++) {
            uint2 v[8];
#pragma unroll
            for (int k = 0; k < 8; k++)
                v[k] = __ldg(xsrc + (size_t)idx[k] * 16 + lane);
            if (c + 1 < nch) {
                const int* p = nb + (c + 1) * 8;
#pragma unroll
                for (int k = 0; k < 8; k++) idx[k] = __ldg(p + k);
            }
#pragma unroll
            for (int k = 0; k < 8; k++) {
                float2 lo = __half22float2(*(const __half2*)&v[k].x);
                float2 hi = __half22float2(*(const __half2*)&v[k].y);
                if (k & 1) {
                    b01 = fadd2(b01, pack2(lo.x, lo.y));
                    b23 = fadd2(b23, pack2(hi.x, hi.y));
                } else {
                    a01 = fadd2(a01, pack2(lo.x, lo.y));
                    a23 = fadd2(a23, pack2(hi.x, hi.y));
                }
            }
        }
    }
    for (int i = nch * 8; i < deg; i++) {
        int n0 = __ldg(nb + i);
        uint2 v = __ldg(xsrc + (size_t)n0 * 16 + lane);
        float2 lo = __half22float2(*(const __half2*)&v.x);
        float2 hi = __half22float2(*(const __half2*)&v.y);
        a01 = fadd2(a01, pack2(lo.x, lo.y));
        a23 = fadd2(a23, pack2(hi.x, hi.y));
    }
    float a0, a1, a2, a3, b0, b1, b2, b3;
    unpack2(a01, a0, a1); unpack2(a23, a2, a3);
    unpack2(b01, b0, b1); unpack2(b23, b2, b3);
    float inv = deg > 0 ? 1.0f / (float)deg : 0.0f;   // deg==0 -> mean 0, matches reference
    float4 o;
    o.x = (a0 + b0) * inv; o.y = (a1 + b1) * inv;
    o.z = (a2 + b2) * inv; o.w = (a3 + b3) * inv;
    mean[(size_t)node * 16 + lane] = o;
}

// ---------------- SAGE transform, both edge types fused into one launch ----------------
// out = mean@Wl^T + bl + x@Wr^T (optional relu). mean fp32, x fp16, out fp16.
template<bool RELU>
__global__ __launch_bounds__(256) void transform2_kernel(
    const float* __restrict__ mean_m, const __half* __restrict__ xd_m,
    const float* __restrict__ Wl_m, const float* __restrict__ bl_m,
    const float* __restrict__ Wr_m, __half* __restrict__ out_m,
    const float* __restrict__ mean_u, const __half* __restrict__ xd_u,
    const float* __restrict__ Wl_u, const float* __restrict__ bl_u,
    const float* __restrict__ Wr_u, __half* __restrict__ out_u,
    int nb_m)
{
    __shared__ float4 sm[4][8][2][16];
    const float *mean, *Wl, *bl, *Wr; const __half* xd; __half* out; int n, bid, nb;
    if ((int)blockIdx.x < nb_m) {
        mean = mean_m; xd = xd_m; Wl = Wl_m; bl = bl_m; Wr = Wr_m; out = out_m;
        n = N_MOVIES; bid = blockIdx.x; nb = nb_m;
    } else {
        mean = mean_u; xd = xd_u; Wl = Wl_u; bl = bl_u; Wr = Wr_u; out = out_u;
        n = N_USERS; bid = blockIdx.x - nb_m; nb = gridDim.x - nb_m;
    }
    int j = threadIdx.x & 63, g = threadIdx.x >> 6;
    unsigned long long wl01[16], wl23[16], wr01[16], wr23[16];
#pragma unroll
    for (int k = 0; k < 16; k++) {
        float4 a = __ldg((const float4*)Wl + j * 16 + k);
        wl01[k] = pack2(a.x, a.y); wl23[k] = pack2(a.z, a.w);
        float4 b = __ldg((const float4*)Wr + j * 16 + k);
        wr01[k] = pack2(b.x, b.y); wr23[k] = pack2(b.z, b.w);
    }
    float bj = __ldg(bl + j);
    for (int r0 = bid * 32; r0 < n; r0 += nb * 32) {
        int rbase = r0 + g * 8;
        // xd: 8 rows x 8 uint4 (fp16) = 64 items, 1 per thread; convert to fp32 in smem
        {
            int row = j >> 3, q = j & 7;
            int r = rbase + row;
            if (r < n) {
                uint4 u = __ldg((const uint4*)(xd + (size_t)r * 64) + q);
                float2 f0 = __half22float2(*(const __half2*)&u.x);
                float2 f1 = __half22float2(*(const __half2*)&u.y);
                float2 f2 = __half22float2(*(const __half2*)&u.z);
                float2 f3 = __half22float2(*(const __half2*)&u.w);
                sm[g][row][1][2 * q]     = make_float4(f0.x, f0.y, f1.x, f1.y);
                sm[g][row][1][2 * q + 1] = make_float4(f2.x, f2.y, f3.x, f3.y);
            }
        }
        // mean: 8 rows x 16 float4 = 128 items, 2 per thread
#pragma unroll
        for (int p = 0; p < 2; p++) {
            int item = p * 64 + j;
            int row = item >> 4, col = item & 15;
            int r = rbase + row;
            if (r < n)
                sm[g][row][0][col] = __ldg((const float4*)mean + (size_t)r * 16 + col);
        }
        __syncthreads();
#pragma unroll
        for (int rr = 0; rr < 8; rr++) {
            int r = rbase + rr;
            if (r < n) {
                unsigned long long p0 = 0, p1 = 0, p2 = 0, p3 = 0;
#pragma unroll
                for (int k = 0; k < 16; k++) {
                    ulonglong2 m = *(const ulonglong2*)&sm[g][rr][0][k];
                    ulonglong2 x = *(const ulonglong2*)&sm[g][rr][1][k];
                    p0 = ffma2(m.x, wl01[k], p0);
                    p1 = ffma2(m.y, wl23[k], p1);
                    p2 = ffma2(x.x, wr01[k], p2);
                    p3 = ffma2(x.y, wr23[k], p3);
                }
                float a0, a1, a2, a3, a4, a5, a6, a7;
                unpack2(p0, a0, a1); unpack2(p1, a2, a3);
                unpack2(p2, a4, a5); unpack2(p3, a6, a7);
                float res = bj + (((a0 + a1) + (a2 + a3)) + ((a4 + a5) + (a6 + a7)));
                if (RELU) res = fmaxf(res, 0.0f);
                out[(size_t)r * 64 + j] = __float2half(res);
            }
        }
        __syncthreads();
    }
}

// ---------------- dot-product decoder (half-warp per edge, fp16 inputs) ----------------
__global__ void decode_kernel(const __half* __restrict__ ou, const __half* __restrict__ om,
                              const int* __restrict__ ls, const int* __restrict__ ld,
                              float* __restrict__ out, int n)
{
    int e = (blockIdx.x * blockDim.x + threadIdx.x) >> 4;
    int lane = threadIdx.x & 15;
    if (e >= n) return;
    int u = __ldg(ls + e), m = __ldg(ld + e);
    uint2 av = __ldg((const uint2*)ou + (size_t)u * 16 + lane);
    uint2 bv = __ldg((const uint2*)om + (size_t)m * 16 + lane);
    float2 a0 = __half22float2(*(const __half2*)&av.x);
    float2 a1 = __half22float2(*(const __half2*)&av.y);
    float2 b0 = __half22float2(*(const __half2*)&bv.x);
    float2 b1 = __half22float2(*(const __half2*)&bv.y);
    float p = a0.x * b0.x + a0.y * b0.y + a1.x * b1.x + a1.y * b1.y;
    p += __shfl_xor_sync(0xffffffffu, p, 1);
    p += __shfl_xor_sync(0xffffffffu, p, 2);
    p += __shfl_xor_sync(0xffffffffu, p, 4);
    p += __shfl_xor_sync(0xffffffffu, p, 8);
    if (lane == 0) out[e] = p;
}

// ---------------- launch ----------------
extern "C" void kernel_launch(void* const* d_in, const int* in_sizes, int n_in,
                              void* d_out, int out_size)
{
    const float* movie_x   = (const float*)d_in[0];
    const int*   user_nid  = (const int*)d_in[1];
    const int*   movie_nid = (const int*)d_in[2];
    const int*   e_src     = (const int*)d_in[3];
    const int*   e_dst     = (const int*)d_in[4];
    const int*   l_src     = (const int*)d_in[5];
    const int*   l_dst     = (const int*)d_in[6];
    const float* user_emb  = (const float*)d_in[7];
    const float* movie_emb = (const float*)d_in[8];
    const float* lin_W     = (const float*)d_in[9];
    const float* lin_b     = (const float*)d_in[10];
    const float* W_l_um1 = (const float*)d_in[11];
    const float* b_l_um1 = (const float*)d_in[12];
    const float* W_r_um1 = (const float*)d_in[13];
    const float* W_l_mu1 = (const float*)d_in[14];
    const float* b_l_mu1 = (const float*)d_in[15];
    const float* W_r_mu1 = (const float*)d_in[16];
    const float* W_l_um2 = (const float*)d_in[17];
    const float* b_l_um2 = (const float*)d_in[18];
    const float* W_r_um2 = (const float*)d_in[19];
    const float* W_l_mu2 = (const float*)d_in[20];
    const float* b_l_mu2 = (const float*)d_in[21];
    const float* W_r_mu2 = (const float*)d_in[22];
    float* out = (float*)d_out;

    float *mu, *mm;
    __half *x16u, *x16m, *h16u, *h16m;
    cudaGetSymbolAddress((void**)&mu, g_mu);
    cudaGetSymbolAddress((void**)&mm, g_mm);
    cudaGetSymbolAddress((void**)&x16u, g_x16u);
    cudaGetSymbolAddress((void**)&x16m, g_x16m);
    cudaGetSymbolAddress((void**)&h16u, g_h16u);
    cudaGetSymbolAddress((void**)&h16m, g_h16m);

    // CSR build (reused by both layers, both directions)
    zero_deg_kernel<<<(NU_PAD / 4 + 255) / 256, 256>>>();
    hist_kernel<<<(N_EDGES / 4 + 255) / 256, 256>>>((const int4*)e_src, (const int4*)e_dst);
    scan_kernel<<<2, 1024>>>();   // also writes cursors
    scatter_kernel<<<(N_EDGES / 4 + 255) / 256, 256>>>((const int4*)e_src, (const int4*)e_dst);

    // feature init (fp16)
    gather_user_kernel<<<(N_USERS * 16 + 255) / 256, 256>>>(user_emb, user_nid, x16u);
    movie_init_kernel<<<592, 256>>>(movie_x, lin_W, lin_b, movie_emb, movie_nid,
                                    x16m, N_MOVIES);

    const int AGG_BLOCKS = ((N_MOVIES + N_USERS) * 16 + 255) / 256;

    // layer 1 (+relu)
    aggregate2_kernel<<<AGG_BLOCKS, 256>>>(x16u, x16m, mm, mu);
    transform2_kernel<true><<<592, 256>>>(mm, x16m, W_l_um1, b_l_um1, W_r_um1, h16m,
                                          mu, x16u, W_l_mu1, b_l_mu1, W_r_mu1, h16u, 197);

    // layer 2 (no activation); outputs overwrite x16 buffers
    aggregate2_kernel<<<AGG_BLOCKS, 256>>>(h16u, h16m, mm, mu);
    transform2_kernel<false><<<592, 256>>>(mm, h16m, W_l_um2, b_l_um2, W_r_um2, x16m,
                                           mu, h16u, W_l_mu2, b_l_mu2, W_r_mu2, x16u, 197);

    // decoder
    decode_kernel<<<(N_LABEL * 16 + 255) / 256, 256>>>(x16u, x16m, l_src, l_dst, out, N_LABEL);
}

// round 5
// speedup vs baseline: 1.4904x; 1.4409x over previous
#include <cuda_runtime.h>
#include <cuda_fp16.h>

#define HIDDEN    64
#define N_USERS   100000
#define N_MOVIES  50000
#define MOVIE_FEAT 128
#define N_EDGES   2000000
#define N_LABEL   500000

// padded so the single-block scans can read int4 past n without guards
#define NM_PAD (N_MOVIES + 8192)
#define NU_PAD (N_USERS  + 8192)

// ---------------- device scratch (allocation-free rule: __device__ globals) ----------------
__device__ __align__(16) int g_deg_m[NM_PAD];
__device__ __align__(16) int g_deg_u[NU_PAD];
__device__ __align__(16) int g_off_m[NM_PAD];
__device__ __align__(16) int g_off_u[NU_PAD];
__device__ __align__(16) int g_cur_m[NM_PAD];
__device__ __align__(16) int g_cur_u[NU_PAD];
__device__ int g_csr_m[N_EDGES];   // neighbors (user idx) of each movie, CSR by movie
__device__ int g_csr_u[N_EDGES];   // neighbors (movie idx) of each user, CSR by user
// fp16 node feature buffers; fp32 buffers hold means, then (layer 2, in-place) final outputs
__device__ __align__(16) __half g_x16u[N_USERS  * HIDDEN];
__device__ __align__(16) __half g_x16m[N_MOVIES * HIDDEN];
__device__ __align__(16) __half g_h16u[N_USERS  * HIDDEN];
__device__ __align__(16) __half g_h16m[N_MOVIES * HIDDEN];
__device__ __align__(16) float g_mu[N_USERS  * HIDDEN];
__device__ __align__(16) float g_mm[N_MOVIES * HIDDEN];

// ---------------- packed f32x2 helpers ----------------
__device__ __forceinline__ unsigned long long pack2(float lo, float hi)
{
    unsigned long long r;
    asm("mov.b64 %0, {%1, %2};" : "=l"(r) : "f"(lo), "f"(hi));
    return r;
}
__device__ __forceinline__ void unpack2(unsigned long long v, float& lo, float& hi)
{
    asm("mov.b64 {%0, %1}, %2;" : "=f"(lo), "=f"(hi) : "l"(v));
}
__device__ __forceinline__ unsigned long long ffma2(unsigned long long a,
                                                    unsigned long long b,
                                                    unsigned long long c)
{
    unsigned long long d;
    asm("fma.rn.f32x2 %0, %1, %2, %3;" : "=l"(d) : "l"(a), "l"(b), "l"(c));
    return d;
}
__device__ __forceinline__ unsigned long long fadd2(unsigned long long a,
                                                    unsigned long long b)
{
    unsigned long long d;
    asm("add.rn.f32x2 %0, %1, %2;" : "=l"(d) : "l"(a), "l"(b));
    return d;
}

// ---------------- CSR build ----------------
__global__ void zero_deg_kernel()
{
    int i = blockIdx.x * blockDim.x + threadIdx.x;
    int4 z = make_int4(0, 0, 0, 0);
    if (i < NM_PAD / 4) ((int4*)g_deg_m)[i] = z;
    if (i < NU_PAD / 4) ((int4*)g_deg_u)[i] = z;
}

__global__ void hist_kernel(const int4* __restrict__ src4, const int4* __restrict__ dst4)
{
    int i = blockIdx.x * blockDim.x + threadIdx.x;
    if (i >= N_EDGES / 4) return;
    int4 s = __ldg(src4 + i), d = __ldg(dst4 + i);
    atomicAdd(&g_deg_u[s.x], 1); atomicAdd(&g_deg_u[s.y], 1);
    atomicAdd(&g_deg_u[s.z], 1); atomicAdd(&g_deg_u[s.w], 1);
    atomicAdd(&g_deg_m[d.x], 1); atomicAdd(&g_deg_m[d.y], 1);
    atomicAdd(&g_deg_m[d.z], 1); atomicAdd(&g_deg_m[d.w], 1);
}

// block 0 scans movie degrees, block 1 scans user degrees; also initializes cursors
__global__ __launch_bounds__(1024) void scan_kernel()
{
    int n; int* deg; int* off; int* cur;
    if (blockIdx.x == 0) { n = N_MOVIES; deg = g_deg_m; off = g_off_m; cur = g_cur_m; }
    else                 { n = N_USERS;  deg = g_deg_u; off = g_off_u; cur = g_cur_u; }
    int chunk = ((((n + 1023) >> 10) + 3) & ~3);   // multiple of 4 for int4
    int t = threadIdx.x;
    int start = t * chunk;

    int s = 0;
    for (int i = 0; i < chunk; i += 4) {
        int4 v = *(const int4*)(deg + start + i);
        s += v.x + v.y + v.z + v.w;
    }
    __shared__ int sh[1024];
    sh[t] = s; __syncthreads();
    for (int d = 1; d < 1024; d <<= 1) {
        int v = (t >= d) ? sh[t - d] : 0;
        __syncthreads();
        sh[t] += v;
        __syncthreads();
    }
    int run = t ? sh[t - 1] : 0;
    for (int i = 0; i < chunk; i += 4) {
        int4 v = *(const int4*)(deg + start + i);
        int4 o;
        o.x = run; run += v.x;
        o.y = run; run += v.y;
        o.z = run; run += v.z;
        o.w = run; run += v.w;
        *(int4*)(off + start + i) = o;
        *(int4*)(cur + start + i) = o;
    }
}

__global__ void scatter_kernel(const int4* __restrict__ src4, const int4* __restrict__ dst4)
{
    int i = blockIdx.x * blockDim.x + threadIdx.x;
    if (i >= N_EDGES / 4) return;
    int4 s = __ldg(src4 + i), d = __ldg(dst4 + i);
    g_csr_m[atomicAdd(&g_cur_m[d.x], 1)] = s.x;
    g_csr_u[atomicAdd(&g_cur_u[s.x], 1)] = d.x;
    g_csr_m[atomicAdd(&g_cur_m[d.y], 1)] = s.y;
    g_csr_u[atomicAdd(&g_cur_u[s.y], 1)] = d.y;
    g_csr_m[atomicAdd(&g_cur_m[d.z], 1)] = s.z;
    g_csr_u[atomicAdd(&g_cur_u[s.z], 1)] = d.z;
    g_csr_m[atomicAdd(&g_cur_m[d.w], 1)] = s.w;
    g_csr_u[atomicAdd(&g_cur_u[s.w], 1)] = d.w;
}

// ---------------- feature init ----------------
__global__ void gather_user_kernel(const float* __restrict__ emb,
                                   const int* __restrict__ nid,
                                   __half* __restrict__ xu16)
{
    int i = blockIdx.x * blockDim.x + threadIdx.x;   // over N_USERS*16 float4s
    if (i >= N_USERS * 16) return;
    int r = i >> 4, c = i & 15;
    float4 v = __ldg((const float4*)emb + nid[r] * 16 + c);
    __half2 h0 = __floats2half2_rn(v.x, v.y);
    __half2 h1 = __floats2half2_rn(v.z, v.w);
    uint2 o;
    o.x = *(unsigned int*)&h0;
    o.y = *(unsigned int*)&h1;
    ((uint2*)xu16)[i] = o;
}

// x_movie = movie_x @ lin_W^T + lin_b + movie_emb[movie_nid]
__global__ __launch_bounds__(256) void movie_init_kernel(
    const float* __restrict__ movie_x, const float* __restrict__ lin_W,
    const float* __restrict__ lin_b,  const float* __restrict__ movie_emb,
    const int* __restrict__ movie_nid, __half* __restrict__ xm16, int n)
{
    __shared__ float4 srow[4][8][32];
    int j = threadIdx.x & 63, g = threadIdx.x >> 6;
    unsigned long long w01[32], w23[32];
#pragma unroll
    for (int k = 0; k < 32; k++) {
        float4 t = __ldg((const float4*)lin_W + j * 32 + k);
        w01[k] = pack2(t.x, t.y);
        w23[k] = pack2(t.z, t.w);
    }
    float bj = __ldg(lin_b + j);
    for (int r0 = blockIdx.x * 32; r0 < n; r0 += gridDim.x * 32) {
        int rbase = r0 + g * 8;
#pragma unroll
        for (int p = 0; p < 4; p++) {
            int item = p * 64 + j;
            int row = item >> 5, col = item & 31;
            int r = rbase + row;
            if (r < n)
                srow[g][row][col] = __ldg((const float4*)movie_x + (size_t)r * 32 + col);
        }
        __syncthreads();
#pragma unroll
        for (int rr = 0; rr < 8; rr++) {
            int r = rbase + rr;
            if (r < n) {
                unsigned long long p0 = 0, p1 = 0;
#pragma unroll
                for (int k = 0; k < 32; k++) {
                    ulonglong2 v = *(const ulonglong2*)&srow[g][rr][k];
                    p0 = ffma2(v.x, w01[k], p0);
                    p1 = ffma2(v.y, w23[k], p1);
                }
                float a0, a1, a2, a3;
                unpack2(p0, a0, a1); unpack2(p1, a2, a3);
                int nid = __ldg(movie_nid + r);
                float res = (a0 + a1) + (a2 + a3) + bj +
                            __ldg(movie_emb + (size_t)nid * 64 + j);
                xm16[(size_t)r * 64 + j] = __float2half(res);
            }
        }
        __syncthreads();
    }
}

// ---------------- segment mean, both directions fused, software-pipelined ----------------
__global__ void aggregate2_kernel(const __half* __restrict__ src_for_m,  // user feats fp16
                                  const __half* __restrict__ src_for_u,  // movie feats fp16
                                  float* __restrict__ out_m, float* __restrict__ out_u)
{
    int h = (blockIdx.x * blockDim.x + threadIdx.x) >> 4;
    int lane = threadIdx.x & 15;
    const uint2* xsrc; const int* csr; const int* off; float4* mean; int node;
    if (h < N_MOVIES) {
        node = h; xsrc = (const uint2*)src_for_m; csr = g_csr_m; off = g_off_m;
        mean = (float4*)out_m;
    } else {
        node = h - N_MOVIES;
        if (node >= N_USERS) return;
        xsrc = (const uint2*)src_for_u; csr = g_csr_u; off = g_off_u;
        mean = (float4*)out_u;
    }
    int s0 = __ldg(off + node);
    int deg = __ldg(off + node + 1) - s0;
    const int* nb = csr + s0;

    unsigned long long a01 = 0, a23 = 0, b01 = 0, b23 = 0;
    int nch = deg >> 3;
    int idx[8];
    if (nch > 0) {
#pragma unroll
        for (int k = 0; k < 8; k++) idx[k] = __ldg(nb + k);
        for (int c = 0; c < nch; c++) {
            uint2 v[8];
#pragma unroll
            for (int k = 0; k < 8; k++)
                v[k] = __ldg(xsrc + (size_t)idx[k] * 16 + lane);
            if (c + 1 < nch) {
                const int* p = nb + (c + 1) * 8;
#pragma unroll
                for (int k = 0; k < 8; k++) idx[k] = __ldg(p + k);
            }
#pragma unroll
            for (int k = 0; k < 8; k++) {
                float2 lo = __half22float2(*(const __half2*)&v[k].x);
                float2 hi = __half22float2(*(const __half2*)&v[k].y);
                if (k & 1) {
                    b01 = fadd2(b01, pack2(lo.x, lo.y));
                    b23 = fadd2(b23, pack2(hi.x, hi.y));
                } else {
                    a01 = fadd2(a01, pack2(lo.x, lo.y));
                    a23 = fadd2(a23, pack2(hi.x, hi.y));
                }
            }
        }
    }
    for (int i = nch * 8; i < deg; i++) {
        int n0 = __ldg(nb + i);
        uint2 v = __ldg(xsrc + (size_t)n0 * 16 + lane);
        float2 lo = __half22float2(*(const __half2*)&v.x);
        float2 hi = __half22float2(*(const __half2*)&v.y);
        a01 = fadd2(a01, pack2(lo.x, lo.y));
        a23 = fadd2(a23, pack2(hi.x, hi.y));
    }
    float a0, a1, a2, a3, b0, b1, b2, b3;
    unpack2(a01, a0, a1); unpack2(a23, a2, a3);
    unpack2(b01, b0, b1); unpack2(b23, b2, b3);
    float inv = deg > 0 ? 1.0f / (float)deg : 0.0f;
    float4 o;
    o.x = (a0 + b0) * inv; o.y = (a1 + b1) * inv;
    o.z = (a2 + b2) * inv; o.w = (a3 + b3) * inv;
    mean[(size_t)node * 16 + lane] = o;
}

// ---------------- SAGE transform via mma.sync m16n8k16 (fp16 in, fp32 accum) --------------
// out[row][j] = sum_k A[row][k] * B[k][j] + bias[j], A = [mean(fp32->fp16) | x(fp16)],
// B[k][j] = k<64 ? Wl[j][k] : Wr[j][k-64]. One 128-row tile per block, 8 warps x 16 rows.
// L1: relu + fp16 output. !L1: fp32 output (may alias the mean buffer; each row is staged
// into smem before any write, and rows are block-private, so in-place is safe).
#define A_STRIDE 136   // halfs per A/B smem row (128 + 8 pad -> conflict-free frag loads)

template<bool L1>
__global__ __launch_bounds__(256) void mma_transform_kernel(
    const float* __restrict__ mean_m, const __half* __restrict__ xd_m,
    const float* __restrict__ Wl_m, const float* __restrict__ bl_m,
    const float* __restrict__ Wr_m, __half* __restrict__ o16_m, float* __restrict__ o32_m,
    const float* __restrict__ mean_u, const __half* __restrict__ xd_u,
    const float* __restrict__ Wl_u, const float* __restrict__ bl_u,
    const float* __restrict__ Wr_u, __half* __restrict__ o16_u, float* __restrict__ o32_u,
    int nb_m)
{
    extern __shared__ char smem[];
    __half* As = (__half*)smem;                       // [128][A_STRIDE]
    __half* Bs = As + 128 * A_STRIDE;                 // [64][A_STRIDE]
    float* bias_s = (float*)(Bs + 64 * A_STRIDE);     // [64]

    const float *mean, *Wl, *bl, *Wr; const __half* xd; __half* o16; float* o32;
    int n, base;
    if ((int)blockIdx.x < nb_m) {
        mean = mean_m; xd = xd_m; Wl = Wl_m; bl = bl_m; Wr = Wr_m;
        o16 = o16_m; o32 = o32_m; n = N_MOVIES; base = blockIdx.x * 128;
    } else {
        mean = mean_u; xd = xd_u; Wl = Wl_u; bl = bl_u; Wr = Wr_u;
        o16 = o16_u; o32 = o32_u; n = N_USERS; base = (blockIdx.x - nb_m) * 128;
    }
    int tid = threadIdx.x;

    // stage B: 64 j-rows x 64 half2 pairs
#pragma unroll
    for (int t = 0; t < 16; t++) {
        int idx = t * 256 + tid;          // 0..4095
        int j = idx >> 6, p = idx & 63;   // pair p covers k = 2p, 2p+1
        int k = 2 * p;
        float2 w;
        if (k < 64) w = __ldg((const float2*)(Wl + j * 64 + k));
        else        w = __ldg((const float2*)(Wr + j * 64 + (k - 64)));
        *(__half2*)(Bs + j * A_STRIDE + k) = __floats2half2_rn(w.x, w.y);
    }
    if (tid < 64) bias_s[tid] = __ldg(bl + tid);

    // stage A mean part: 128 rows x 32 half2 pairs (cols 0..63)
#pragma unroll
    for (int t = 0; t < 16; t++) {
        int idx = t * 256 + tid;          // 0..4095
        int r = idx >> 5, p = idx & 31;
        __half2 h = __floats2half2_rn(0.f, 0.f);
        if (base + r < n) {
            float2 v = __ldg((const float2*)(mean + (size_t)(base + r) * 64 + 2 * p));
            h = __floats2half2_rn(v.x, v.y);
        }
        *(__half2*)(As + r * A_STRIDE + 2 * p) = h;
    }
    // stage A x part: 128 rows x 8 uint4 (cols 64..127, fp16 direct)
#pragma unroll
    for (int t = 0; t < 4; t++) {
        int idx = t * 256 + tid;          // 0..1023
        int r = idx >> 3, q = idx & 7;
        uint4 u = make_uint4(0, 0, 0, 0);
        if (base + r < n)
            u = __ldg((const uint4*)(xd + (size_t)(base + r) * 64) + q);
        *(uint4*)(As + r * A_STRIDE + 64 + q * 8) = u;
    }
    __syncthreads();

    int warp = tid >> 5, lane = tid & 31;
    int grp = lane >> 2, tig = lane & 3;
    int r0 = warp * 16;
    float acc[8][4];
#pragma unroll
    for (int nt = 0; nt < 8; nt++)
#pragma unroll
        for (int c = 0; c < 4; c++) acc[nt][c] = 0.f;

#pragma unroll
    for (int kt = 0; kt < 8; kt++) {
        int ar = r0 + grp, ac = kt * 16 + tig * 2;
        unsigned a0 = *(const unsigned*)(As + ar * A_STRIDE + ac);
        unsigned a1 = *(const unsigned*)(As + (ar + 8) * A_STRIDE + ac);
        unsigned a2 = *(const unsigned*)(As + ar * A_STRIDE + ac + 8);
        unsigned a3 = *(const unsigned*)(As + (ar + 8) * A_STRIDE + ac + 8);
#pragma unroll
        for (int nt = 0; nt < 8; nt++) {
            int bn = nt * 8 + grp, bk = kt * 16 + tig * 2;
            unsigned b0 = *(const unsigned*)(Bs + bn * A_STRIDE + bk);
            unsigned b1 = *(const unsigned*)(Bs + bn * A_STRIDE + bk + 8);
            asm volatile(
                "mma.sync.aligned.m16n8k16.row.col.f32.f16.f16.f32 "
                "{%0,%1,%2,%3}, {%4,%5,%6,%7}, {%8,%9}, {%0,%1,%2,%3};"
                : "+f"(acc[nt][0]), "+f"(acc[nt][1]), "+f"(acc[nt][2]), "+f"(acc[nt][3])
                : "r"(a0), "r"(a1), "r"(a2), "r"(a3), "r"(b0), "r"(b1));
        }
    }

    // epilogue
#pragma unroll
    for (int nt = 0; nt < 8; nt++) {
        int col = nt * 8 + tig * 2;
        float bj0 = bias_s[col], bj1 = bias_s[col + 1];
        int gr0 = base + r0 + grp;
        int gr1 = gr0 + 8;
        float v00 = acc[nt][0] + bj0, v01 = acc[nt][1] + bj1;
        float v10 = acc[nt][2] + bj0, v11 = acc[nt][3] + bj1;
        if (L1) {
            v00 = fmaxf(v00, 0.f); v01 = fmaxf(v01, 0.f);
            v10 = fmaxf(v10, 0.f); v11 = fmaxf(v11, 0.f);
            if (gr0 < n) *(__half2*)(o16 + (size_t)gr0 * 64 + col) = __floats2half2_rn(v00, v01);
            if (gr1 < n) *(__half2*)(o16 + (size_t)gr1 * 64 + col) = __floats2half2_rn(v10, v11);
        } else {
            if (gr0 < n) *(float2*)(o32 + (size_t)gr0 * 64 + col) = make_float2(v00, v01);
            if (gr1 < n) *(float2*)(o32 + (size_t)gr1 * 64 + col) = make_float2(v10, v11);
        }
    }
}

// ---------------- dot-product decoder (half-warp per edge, fp32 inputs) ----------------
__global__ void decode_kernel(const float* __restrict__ ou, const float* __restrict__ om,
                              const int* __restrict__ ls, const int* __restrict__ ld,
                              float* __restrict__ out, int n)
{
    int e = (blockIdx.x * blockDim.x + threadIdx.x) >> 4;
    int lane = threadIdx.x & 15;
    if (e >= n) return;
    int u = __ldg(ls + e), m = __ldg(ld + e);
    float4 a = __ldg((const float4*)ou + (size_t)u * 16 + lane);
    float4 b = __ldg((const float4*)om + (size_t)m * 16 + lane);
    float p = a.x * b.x + a.y * b.y + a.z * b.z + a.w * b.w;
    p += __shfl_xor_sync(0xffffffffu, p, 1);
    p += __shfl_xor_sync(0xffffffffu, p, 2);
    p += __shfl_xor_sync(0xffffffffu, p, 4);
    p += __shfl_xor_sync(0xffffffffu, p, 8);
    if (lane == 0) out[e] = p;
}

// ---------------- launch ----------------
extern "C" void kernel_launch(void* const* d_in, const int* in_sizes, int n_in,
                              void* d_out, int out_size)
{
    const float* movie_x   = (const float*)d_in[0];
    const int*   user_nid  = (const int*)d_in[1];
    const int*   movie_nid = (const int*)d_in[2];
    const int*   e_src     = (const int*)d_in[3];
    const int*   e_dst     = (const int*)d_in[4];
    const int*   l_src     = (const int*)d_in[5];
    const int*   l_dst     = (const int*)d_in[6];
    const float* user_emb  = (const float*)d_in[7];
    const float* movie_emb = (const float*)d_in[8];
    const float* lin_W     = (const float*)d_in[9];
    const float* lin_b     = (const float*)d_in[10];
    const float* W_l_um1 = (const float*)d_in[11];
    const float* b_l_um1 = (const float*)d_in[12];
    const float* W_r_um1 = (const float*)d_in[13];
    const float* W_l_mu1 = (const float*)d_in[14];
    const float* b_l_mu1 = (const float*)d_in[15];
    const float* W_r_mu1 = (const float*)d_in[16];
    const float* W_l_um2 = (const float*)d_in[17];
    const float* b_l_um2 = (const float*)d_in[18];
    const float* W_r_um2 = (const float*)d_in[19];
    const float* W_l_mu2 = (const float*)d_in[20];
    const float* b_l_mu2 = (const float*)d_in[21];
    const float* W_r_mu2 = (const float*)d_in[22];
    float* out = (float*)d_out;

    float *mu, *mm;
    __half *x16u, *x16m, *h16u, *h16m;
    cudaGetSymbolAddress((void**)&mu, g_mu);
    cudaGetSymbolAddress((void**)&mm, g_mm);
    cudaGetSymbolAddress((void**)&x16u, g_x16u);
    cudaGetSymbolAddress((void**)&x16m, g_x16m);
    cudaGetSymbolAddress((void**)&h16u, g_h16u);
    cudaGetSymbolAddress((void**)&h16m, g_h16m);

    const int MMA_SMEM = (128 * A_STRIDE + 64 * A_STRIDE) * 2 + 64 * 4;  // 52480B
    cudaFuncSetAttribute(mma_transform_kernel<true>,
                         cudaFuncAttributeMaxDynamicSharedMemorySize, MMA_SMEM);
    cudaFuncSetAttribute(mma_transform_kernel<false>,
                         cudaFuncAttributeMaxDynamicSharedMemorySize, MMA_SMEM);

    // feature init first (independent chain; also puts hist at profiled launch index 3)
    gather_user_kernel<<<(N_USERS * 16 + 255) / 256, 256>>>(user_emb, user_nid, x16u);
    movie_init_kernel<<<592, 256>>>(movie_x, lin_W, lin_b, movie_emb, movie_nid,
                                    x16m, N_MOVIES);

    // CSR build (reused by both layers, both directions)
    zero_deg_kernel<<<(NU_PAD / 4 + 255) / 256, 256>>>();
    hist_kernel<<<(N_EDGES / 4 + 255) / 256, 256>>>((const int4*)e_src, (const int4*)e_dst);
    scan_kernel<<<2, 1024>>>();   // also writes cursors
    scatter_kernel<<<(N_EDGES / 4 + 255) / 256, 256>>>((const int4*)e_src, (const int4*)e_dst);

    const int AGG_BLOCKS = ((N_MOVIES + N_USERS) * 16 + 255) / 256;
    const int NB_M = (N_MOVIES + 127) / 128;   // 391
    const int NB_U = (N_USERS + 127) / 128;    // 782

    // layer 1 (+relu), fp16 outputs
    aggregate2_kernel<<<AGG_BLOCKS, 256>>>(x16u, x16m, mm, mu);
    mma_transform_kernel<true><<<NB_M + NB_U, 256, MMA_SMEM>>>(
        mm, x16m, W_l_um1, b_l_um1, W_r_um1, h16m, nullptr,
        mu, x16u, W_l_mu1, b_l_mu1, W_r_mu1, h16u, nullptr, NB_M);

    // layer 2 (no activation), fp32 outputs in-place over the mean buffers
    aggregate2_kernel<<<AGG_BLOCKS, 256>>>(h16u, h16m, mm, mu);
    mma_transform_kernel<false><<<NB_M + NB_U, 256, MMA_SMEM>>>(
        mm, h16m, W_l_um2, b_l_um2, W_r_um2, nullptr, mm,
        mu, h16u, W_l_mu2, b_l_mu2, W_r_mu2, nullptr, mu, NB_M);

    // decoder (fp32 finals: users in mu, movies in mm)
    decode_kernel<<<(N_LABEL * 16 + 255) / 256, 256>>>(mu, mm, l_src, l_dst, out, N_LABEL);
}